// round 13
// baseline (speedup 1.0000x reference)
#include <cuda_runtime.h>
#include <cstdint>

// Problem constants (fixed instance)
constexpr int S   = 16;
constexpr int EXT = 64;
constexpr int SE  = S * EXT;          // 1024
constexpr int NN  = 8192;             // nodes
constexpr int EE  = 16384;            // edges
constexpr int PP  = 2048;             // paths

// Dense coefficient tensor, duplicated into float2 {c,c} so LDS.128 yields two
// ready f32x2 operands. Layout: idx = (i*16 + j)*16 + k   (k contiguous)
__device__ __align__(16) float2 g_C2[S * S * S];

// ---------------- f32x2 packed helpers (sm_103a) ----------------
__device__ __forceinline__ unsigned long long f32x2_pack(float lo, float hi) {
    unsigned long long d;
    asm("mov.b64 %0, {%1, %2};" : "=l"(d) : "f"(lo), "f"(hi));
    return d;
}
__device__ __forceinline__ void f32x2_unpack(unsigned long long v, float& lo, float& hi) {
    asm("mov.b64 {%0, %1}, %2;" : "=f"(lo), "=f"(hi) : "l"(v));
}
__device__ __forceinline__ unsigned long long f32x2_mul(unsigned long long a, unsigned long long b) {
    unsigned long long d;
    asm("mul.rn.f32x2 %0, %1, %2;" : "=l"(d) : "l"(a), "l"(b));
    return d;
}
__device__ __forceinline__ unsigned long long f32x2_fma(unsigned long long a, unsigned long long b,
                                                        unsigned long long c) {
    unsigned long long d;
    asm("fma.rn.f32x2 %0, %1, %2, %3;" : "=l"(d) : "l"(a), "l"(b), "l"(c));
    return d;
}

// ---------------- setup kernels ----------------
__global__ void zero_c_kernel() {
    int t = blockIdx.x * blockDim.x + threadIdx.x;
    if (t < S * S * S) g_C2[t] = make_float2(0.0f, 0.0f);
}

__global__ void build_c_kernel(const int* __restrict__ path_indices,
                               const float* __restrict__ path_coeffs) {
    int p = blockIdx.x * blockDim.x + threadIdx.x;
    if (p >= PP) return;
    int i = path_indices[3 * p + 0];   // x segment
    int j = path_indices[3 * p + 1];   // y segment
    int k = path_indices[3 * p + 2];   // out segment
    float cf = path_coeffs[p];
    int idx = (i * S + j) * S + k;
    atomicAdd(&g_C2[idx].x, cf);
    atomicAdd(&g_C2[idx].y, cf);
}

__global__ void zero_out_kernel(float4* __restrict__ out, int n4) {
    int t = blockIdx.x * blockDim.x + threadIdx.x;
    if (t < n4) out[t] = make_float4(0.0f, 0.0f, 0.0f, 0.0f);
}

// ---------------- main contraction ----------------
// R13 decomposition: each thread owns 1 edge x 4 channels x 8 k-values.
//   channels: pair A = (c, c+32), pair B = (c+16, c+48), c = lane & 15
//   k-half:   kh = warp & 1  (warp-uniform -> LDS broadcast, N=1)
//   edge:     e = block*4 + (warp>>1)*2 + (lane>>4)
// Per (i,j) per thread: 4 LDS.128 feed 16 FFMA2 (same 4:1 warp ratio and same
// chip totals as the 188.9us R4 kernel), but register core is only ~64 regs
// (acc 32 + y 32) -> 4 blocks/SM = 4 warps/SMSP for latency coverage.
constexpr int EDGES_PER_BLOCK = 4;
constexpr int JC = 8;                  // j-chunk size (two chunks)

__global__ __launch_bounds__(128, 4) void seg_poly_kernel(
    const float* __restrict__ x,
    const float* __restrict__ y,
    const int*   __restrict__ idx_in,
    const int*   __restrict__ idx_out,
    float*       __restrict__ out)
{
    __shared__ __align__(16) float2 Cs[S * S * S];   // 32 KB

    // cooperative load of C (vectorized)
    {
        const float4* src = reinterpret_cast<const float4*>(g_C2);
        float4* dst = reinterpret_cast<float4*>(Cs);
        for (int t = threadIdx.x; t < (S * S * S) / 2; t += 128)
            dst[t] = src[t];
    }
    __syncthreads();

    const int w    = threadIdx.x >> 5;       // warp 0..3
    const int lane = threadIdx.x & 31;
    const int kh   = w & 1;                  // k-half (warp-uniform)
    const int s    = lane >> 4;              // edge slot 0/1
    const int c    = lane & 15;              // base channel

    const int e = blockIdx.x * EDGES_PER_BLOCK + (w >> 1) * 2 + s;

    const int xrow = idx_in[e];
    const int orow = idx_out[e];

    const float* xp = x + (size_t)xrow * SE + c;
    const float* yp = y + (size_t)e    * SE + c;

    // acc[pair][k8] : 2*8 f32x2 = 32 regs
    unsigned long long accA[8], accB[8];
    #pragma unroll
    for (int k = 0; k < 8; ++k) { accA[k] = 0ULL; accB[k] = 0ULL; }

    #pragma unroll 1
    for (int jc = 0; jc < S; jc += JC) {
        // y chunk: 2 pairs x JC f32x2 = 32 regs
        unsigned long long yA[JC], yB[JC];
        {
            const float* q = yp + jc * EXT;
            #pragma unroll
            for (int j = 0; j < JC; ++j) {
                yA[j] = f32x2_pack(q[j * EXT     ], q[j * EXT + 32]);
                yB[j] = f32x2_pack(q[j * EXT + 16], q[j * EXT + 48]);
            }
        }

        const float2* crow = Cs + (jc * S) + kh * 8;   // advance by S*S per i
        const float* xq = xp;
        // 2-deep prefetch pipeline on the 4 x scalars
        float xa0 = xq[0], xa1 = xq[32], xb0 = xq[16], xb1 = xq[48];
        #pragma unroll 1
        for (int i = 0; i < S; ++i) {
            const unsigned long long aA = f32x2_pack(xa0, xa1);
            const unsigned long long aB = f32x2_pack(xb0, xb1);
            if (i + 1 < S) {
                xq += EXT;
                xa0 = xq[0]; xa1 = xq[32]; xb0 = xq[16]; xb1 = xq[48];
            }

            #pragma unroll
            for (int j = 0; j < JC; ++j) {
                const unsigned long long pA = f32x2_mul(aA, yA[j]);
                const unsigned long long pB = f32x2_mul(aB, yB[j]);
                const ulonglong2* cp = reinterpret_cast<const ulonglong2*>(crow + j * S);
                #pragma unroll
                for (int kk = 0; kk < 4; ++kk) {
                    ulonglong2 cc = cp[kk];           // LDS.128: this warp's k-half
                    accA[2 * kk]     = f32x2_fma(cc.x, pA, accA[2 * kk]);
                    accB[2 * kk]     = f32x2_fma(cc.x, pB, accB[2 * kk]);
                    accA[2 * kk + 1] = f32x2_fma(cc.y, pA, accA[2 * kk + 1]);
                    accB[2 * kk + 1] = f32x2_fma(cc.y, pB, accB[2 * kk + 1]);
                }
            }
            crow += S * S;
        }
    }

    // scatter-add: 8 k x 4 channels = 32 atomics/thread
    {
        float* op = out + (size_t)orow * SE + kh * 8 * EXT + c;
        #pragma unroll
        for (int k = 0; k < 8; ++k) {
            float a0, a1, b0, b1;
            f32x2_unpack(accA[k], a0, a1);
            f32x2_unpack(accB[k], b0, b1);
            atomicAdd(op + k * EXT,      a0);
            atomicAdd(op + k * EXT + 16, b0);
            atomicAdd(op + k * EXT + 32, a1);
            atomicAdd(op + k * EXT + 48, b1);
        }
    }
}

// ---------------- launch ----------------
extern "C" void kernel_launch(void* const* d_in, const int* in_sizes, int n_in,
                              void* d_out, int out_size)
{
    const float* x        = (const float*)d_in[0];
    const float* y        = (const float*)d_in[1];
    const int*   idx_in   = (const int*)d_in[2];
    const int*   idx_out  = (const int*)d_in[3];
    const int*   path_idx = (const int*)d_in[4];
    const float* path_cf  = (const float*)d_in[5];
    float* out = (float*)d_out;

    zero_c_kernel<<<(S * S * S + 255) / 256, 256>>>();
    build_c_kernel<<<(PP + 255) / 256, 256>>>(path_idx, path_cf);

    int n4 = out_size / 4;  // 8M floats -> 2M float4
    zero_out_kernel<<<(n4 + 511) / 512, 512>>>((float4*)d_out, n4);

    seg_poly_kernel<<<EE / EDGES_PER_BLOCK, 128>>>(x, y, idx_in, idx_out, out);
}

// round 14
// speedup vs baseline: 1.6604x; 1.6604x over previous
#include <cuda_runtime.h>
#include <cstdint>

// Problem constants (fixed instance)
constexpr int S   = 16;
constexpr int EXT = 64;
constexpr int SE  = S * EXT;          // 1024
constexpr int NN  = 8192;             // nodes
constexpr int EE  = 16384;            // edges
constexpr int PP  = 2048;             // paths

// Dense coefficient tensor, duplicated into float2 {c,c} so LDS.128 yields two
// ready f32x2 operands. Layout: idx = (i*16 + j)*16 + k   (k contiguous)
__device__ __align__(16) float2 g_C2[S * S * S];

// ---------------- f32x2 packed helpers (sm_103a) ----------------
__device__ __forceinline__ unsigned long long f32x2_pack(float lo, float hi) {
    unsigned long long d;
    asm("mov.b64 %0, {%1, %2};" : "=l"(d) : "f"(lo), "f"(hi));
    return d;
}
__device__ __forceinline__ void f32x2_unpack(unsigned long long v, float& lo, float& hi) {
    asm("mov.b64 {%0, %1}, %2;" : "=f"(lo), "=f"(hi) : "l"(v));
}
__device__ __forceinline__ unsigned long long f32x2_mul(unsigned long long a, unsigned long long b) {
    unsigned long long d;
    asm("mul.rn.f32x2 %0, %1, %2;" : "=l"(d) : "l"(a), "l"(b));
    return d;
}
__device__ __forceinline__ unsigned long long f32x2_fma(unsigned long long a, unsigned long long b,
                                                        unsigned long long c) {
    unsigned long long d;
    asm("fma.rn.f32x2 %0, %1, %2, %3;" : "=l"(d) : "l"(a), "l"(b), "l"(c));
    return d;
}

// ---------------- setup kernels ----------------
__global__ void zero_c_kernel() {
    int t = blockIdx.x * blockDim.x + threadIdx.x;
    if (t < S * S * S) g_C2[t] = make_float2(0.0f, 0.0f);
}

__global__ void build_c_kernel(const int* __restrict__ path_indices,
                               const float* __restrict__ path_coeffs) {
    int p = blockIdx.x * blockDim.x + threadIdx.x;
    if (p >= PP) return;
    int i = path_indices[3 * p + 0];   // x segment
    int j = path_indices[3 * p + 1];   // y segment
    int k = path_indices[3 * p + 2];   // out segment
    float cf = path_coeffs[p];
    int idx = (i * S + j) * S + k;
    atomicAdd(&g_C2[idx].x, cf);
    atomicAdd(&g_C2[idx].y, cf);
}

__global__ void zero_out_kernel(float4* __restrict__ out, int n4) {
    int t = blockIdx.x * blockDim.x + threadIdx.x;
    if (t < n4) out[t] = make_float4(0.0f, 0.0f, 0.0f, 0.0f);
}

// ---------------- main contraction ----------------
// R4 shape (best measured: 188.9us): block 128 = 8 edges x 16 lanes; lane c
// owns channels (c, c+32) [pair A, registers] and (c+16, c+48) [pair B].
// R14 change: pair-B y values live in SHARED (16KB) instead of 32 registers,
// cutting the register core so 3 blocks/SM fit (launch_bounds cap) -> 3
// warps/SMSP of latency coverage vs R4's 2. Costs 1 extra LDS.64 per (i,j).
constexpr int EDGES_PER_BLOCK = 8;

__global__ __launch_bounds__(128, 3) void seg_poly_kernel(
    const float* __restrict__ x,
    const float* __restrict__ y,
    const int*   __restrict__ idx_in,
    const int*   __restrict__ idx_out,
    float*       __restrict__ out)
{
    __shared__ __align__(16) float2 Cs[S * S * S];      // 32 KB
    __shared__ __align__(16) float2 yBs[EDGES_PER_BLOCK][S][16];  // 16 KB [edge][j][c]

    // cooperative load of C (vectorized)
    {
        const float4* src = reinterpret_cast<const float4*>(g_C2);
        float4* dst = reinterpret_cast<float4*>(Cs);
        for (int t = threadIdx.x; t < (S * S * S) / 2; t += 128)
            dst[t] = src[t];
    }

    const int le = threadIdx.x >> 4;        // local edge 0..7
    const int c  = threadIdx.x & 15;        // base channel
    const int e  = blockIdx.x * EDGES_PER_BLOCK + le;

    const int xrow = idx_in[e];
    const int orow = idx_out[e];

    const float* xp = x + (size_t)xrow * SE + c;
    const float* yp = y + (size_t)e    * SE + c;

    // stage pair-B y values into shared: yBs[le][j][c] = {y[j,c+16], y[j,c+48]}
    #pragma unroll
    for (int j = 0; j < S; ++j)
        yBs[le][j][c] = make_float2(yp[j * EXT + 16], yp[j * EXT + 48]);

    // pair-A y values in registers
    unsigned long long yvA[S];
    #pragma unroll
    for (int j = 0; j < S; ++j)
        yvA[j] = f32x2_pack(yp[j * EXT], yp[j * EXT + 32]);

    __syncthreads();

    unsigned long long accA[S];
    unsigned long long accB[S];
    #pragma unroll
    for (int k = 0; k < S; ++k) { accA[k] = 0ULL; accB[k] = 0ULL; }

    // base pointer for this thread's yB row (element stride j*16 ull)
    const unsigned long long* ybp =
        reinterpret_cast<const unsigned long long*>(&yBs[le][0][c]);

    // outer i-loop rolled; 2-deep x prefetch pipeline hides L2 gather latency
    const float* xpp = xp;
    float xa0 = xpp[0],  xa1 = xpp[32];
    float xb0 = xpp[16], xb1 = xpp[48];
    #pragma unroll 1
    for (int i = 0; i < S; ++i) {
        const unsigned long long aA = f32x2_pack(xa0, xa1);
        const unsigned long long aB = f32x2_pack(xb0, xb1);
        if (i + 1 < S) {
            xpp += EXT;
            xa0 = xpp[0];  xa1 = xpp[32];
            xb0 = xpp[16]; xb1 = xpp[48];
        }
        const float2* crow = Cs + i * (S * S);
        #pragma unroll
        for (int j = 0; j < S; ++j) {
            const unsigned long long pA = f32x2_mul(aA, yvA[j]);
            const unsigned long long pB = f32x2_mul(aB, ybp[j * 16]);  // LDS.64
            const ulonglong2* cp = reinterpret_cast<const ulonglong2*>(crow + j * S);
            #pragma unroll
            for (int kk = 0; kk < 8; ++kk) {
                ulonglong2 cc = cp[kk];               // LDS.128: {C[2kk]x2, C[2kk+1]x2}
                accA[2 * kk]     = f32x2_fma(cc.x, pA, accA[2 * kk]);
                accB[2 * kk]     = f32x2_fma(cc.x, pB, accB[2 * kk]);
                accA[2 * kk + 1] = f32x2_fma(cc.y, pA, accA[2 * kk + 1]);
                accB[2 * kk + 1] = f32x2_fma(cc.y, pB, accB[2 * kk + 1]);
            }
        }
    }

    // scatter-add (coalesced 64B RED.ADD.F32 segments per k per quarter)
    float* op = out + (size_t)orow * SE + c;
    #pragma unroll
    for (int k = 0; k < S; ++k) {
        float a0, a1, b0, b1;
        f32x2_unpack(accA[k], a0, a1);
        f32x2_unpack(accB[k], b0, b1);
        atomicAdd(op + k * EXT,      a0);
        atomicAdd(op + k * EXT + 16, b0);
        atomicAdd(op + k * EXT + 32, a1);
        atomicAdd(op + k * EXT + 48, b1);
    }
}

// ---------------- launch ----------------
extern "C" void kernel_launch(void* const* d_in, const int* in_sizes, int n_in,
                              void* d_out, int out_size)
{
    const float* x        = (const float*)d_in[0];
    const float* y        = (const float*)d_in[1];
    const int*   idx_in   = (const int*)d_in[2];
    const int*   idx_out  = (const int*)d_in[3];
    const int*   path_idx = (const int*)d_in[4];
    const float* path_cf  = (const float*)d_in[5];
    float* out = (float*)d_out;

    zero_c_kernel<<<(S * S * S + 255) / 256, 256>>>();
    build_c_kernel<<<(PP + 255) / 256, 256>>>(path_idx, path_cf);

    int n4 = out_size / 4;  // 8M floats -> 2M float4
    zero_out_kernel<<<(n4 + 511) / 512, 512>>>((float4*)d_out, n4);

    seg_poly_kernel<<<EE / EDGES_PER_BLOCK, 128>>>(x, y, idx_in, idx_out, out);
}